// round 7
// baseline (speedup 1.0000x reference)
#include <cuda_runtime.h>
#include <cfloat>

// Problem constants (reference: xyz [4, 8192, 3], K=16)
#define BB   4
#define NN   8192
#define GG   32
#define NC   (GG * GG * GG)
#define KK   16
#define SW   8              // warps per search block
#define FULL 0xffffffffu

// ---- device scratch (static: allocation-free) ----
__device__ float4 g_pts[BB][NN];        // cell-sorted points (x,y,z,|x|^2)
__device__ int    g_pidx[BB][NN];       // original indices, cell-sorted
__device__ int    g_cnt[BB][NC];        // per-cell counts
__device__ int    g_cst[BB][NC + 1];    // per-cell start offsets (exclusive scan)
__device__ int    g_cur[BB][NC];        // scatter cursors
__device__ float  g_bb[BB][6];          // minx,miny,minz,maxx,maxy,maxz

__device__ __forceinline__ bool lex_less(float d, int i, float ed, int ei) {
    return (d < ed) || (d == ed && i < ei);
}

// ---- 1: zero counts ----
__global__ void k_init() {
    int i = blockIdx.x * blockDim.x + threadIdx.x;
    if (i < BB * NC) ((int*)g_cnt)[i] = 0;
}

// ---- 2: per-batch bbox (1 block per batch) ----
__global__ void k_bbox(const float* __restrict__ xyz) {
    const int b = blockIdx.x;
    const float* base = xyz + (size_t)b * NN * 3;
    float mn0 = FLT_MAX, mn1 = FLT_MAX, mn2 = FLT_MAX;
    float mx0 = -FLT_MAX, mx1 = -FLT_MAX, mx2 = -FLT_MAX;
    for (int i = threadIdx.x; i < NN; i += blockDim.x) {
        const float x = base[3 * i + 0], y = base[3 * i + 1], z = base[3 * i + 2];
        mn0 = fminf(mn0, x); mx0 = fmaxf(mx0, x);
        mn1 = fminf(mn1, y); mx1 = fmaxf(mx1, y);
        mn2 = fminf(mn2, z); mx2 = fmaxf(mx2, z);
    }
#pragma unroll
    for (int o = 16; o; o >>= 1) {
        mn0 = fminf(mn0, __shfl_xor_sync(FULL, mn0, o));
        mn1 = fminf(mn1, __shfl_xor_sync(FULL, mn1, o));
        mn2 = fminf(mn2, __shfl_xor_sync(FULL, mn2, o));
        mx0 = fmaxf(mx0, __shfl_xor_sync(FULL, mx0, o));
        mx1 = fmaxf(mx1, __shfl_xor_sync(FULL, mx1, o));
        mx2 = fmaxf(mx2, __shfl_xor_sync(FULL, mx2, o));
    }
    __shared__ float s[6][32];
    const int w = threadIdx.x >> 5, l = threadIdx.x & 31;
    if (l == 0) {
        s[0][w] = mn0; s[1][w] = mn1; s[2][w] = mn2;
        s[3][w] = mx0; s[4][w] = mx1; s[5][w] = mx2;
    }
    __syncthreads();
    if (threadIdx.x == 0) {
        const int nw = blockDim.x >> 5;
        float a0 = FLT_MAX, a1 = FLT_MAX, a2 = FLT_MAX;
        float b0 = -FLT_MAX, b1 = -FLT_MAX, b2 = -FLT_MAX;
        for (int i = 0; i < nw; i++) {
            a0 = fminf(a0, s[0][i]); a1 = fminf(a1, s[1][i]); a2 = fminf(a2, s[2][i]);
            b0 = fmaxf(b0, s[3][i]); b1 = fmaxf(b1, s[4][i]); b2 = fmaxf(b2, s[5][i]);
        }
        g_bb[b][0] = a0 - 1e-4f; g_bb[b][1] = a1 - 1e-4f; g_bb[b][2] = a2 - 1e-4f;
        g_bb[b][3] = b0 + 1e-4f; g_bb[b][4] = b1 + 1e-4f; g_bb[b][5] = b2 + 1e-4f;
    }
}

// Cell assignment — SAME formula everywhere (count/scatter/search).
__device__ __forceinline__ int cell1(float v, float mn, float inv) {
    int c = (int)((v - mn) * inv);
    return min(GG - 1, max(0, c));
}

// ---- 3: count points per cell ----
__global__ void k_count(const float* __restrict__ xyz) {
    const int gi = blockIdx.x * blockDim.x + threadIdx.x;
    if (gi >= BB * NN) return;
    const int b = gi / NN, i = gi - b * NN;
    const float* base = xyz + (size_t)b * NN * 3;
    const float x = base[3 * i + 0], y = base[3 * i + 1], z = base[3 * i + 2];
    const float mnx = g_bb[b][0], mny = g_bb[b][1], mnz = g_bb[b][2];
    const float ivx = GG / (g_bb[b][3] - mnx);
    const float ivy = GG / (g_bb[b][4] - mny);
    const float ivz = GG / (g_bb[b][5] - mnz);
    const int cx = cell1(x, mnx, ivx), cy = cell1(y, mny, ivy), cz = cell1(z, mnz, ivz);
    atomicAdd(&g_cnt[b][(cz * GG + cy) * GG + cx], 1);
}

// ---- 4: exclusive scan over NC cells per batch (1 block per batch) ----
__global__ void k_scan() {
    const int b = blockIdx.x;
    const int t = threadIdx.x;                // 1024 threads, 32 cells each
    __shared__ int ss[1024];
    const int base = t * 32;
    int s = 0;
#pragma unroll
    for (int i = 0; i < 32; i++) s += g_cnt[b][base + i];
    ss[t] = s;
    __syncthreads();
    for (int o = 1; o < 1024; o <<= 1) {
        const int v = (t >= o) ? ss[t - o] : 0;
        __syncthreads();
        ss[t] += v;
        __syncthreads();
    }
    int excl = ss[t] - s;
#pragma unroll
    for (int i = 0; i < 32; i++) {
        g_cst[b][base + i] = excl;
        g_cur[b][base + i] = excl;
        excl += g_cnt[b][base + i];
    }
    if (t == 1023) g_cst[b][NC] = excl;       // == NN
}

// ---- 5: scatter points into cell-sorted order ----
__global__ void k_scatter(const float* __restrict__ xyz) {
    const int gi = blockIdx.x * blockDim.x + threadIdx.x;
    if (gi >= BB * NN) return;
    const int b = gi / NN, i = gi - b * NN;
    const float* base = xyz + (size_t)b * NN * 3;
    const float x = base[3 * i + 0], y = base[3 * i + 1], z = base[3 * i + 2];
    const float mnx = g_bb[b][0], mny = g_bb[b][1], mnz = g_bb[b][2];
    const float ivx = GG / (g_bb[b][3] - mnx);
    const float ivy = GG / (g_bb[b][4] - mny);
    const float ivz = GG / (g_bb[b][5] - mnz);
    const int cx = cell1(x, mnx, ivx), cy = cell1(y, mny, ivy), cz = cell1(z, mnz, ivz);
    const int pos = atomicAdd(&g_cur[b][(cz * GG + cy) * GG + cx], 1);
    g_pts[b][pos] = make_float4(x, y, z, x * x + y * y + z * z);   // frozen R1 form
    g_pidx[b][pos] = i;
}

// ---- 6: per-query expanding-ring exact kNN + feature epilogue ----
__global__ __launch_bounds__(SW * 32)
void k_search(const float* __restrict__ xyz, float* __restrict__ out, int out_size) {
    const int lane = threadIdx.x & 31;
    const int wid  = threadIdx.x >> 5;
    const int qg = blockIdx.x * SW + wid;      // 0..BB*NN-1
    const int b = qg >> 13;                    // / NN
    const int q = qg & (NN - 1);
    const int t = lane & 15;

    const float* __restrict__ base = xyz + (size_t)b * NN * 3;
    const float qx = base[3 * q + 0], qy = base[3 * q + 1], qz = base[3 * q + 2];
    const float s0 = qx * qx + qy * qy + qz * qz;          // frozen R1 form

    const float mnx = g_bb[b][0], mny = g_bb[b][1], mnz = g_bb[b][2];
    const float ex = g_bb[b][3] - mnx, ey = g_bb[b][4] - mny, ez = g_bb[b][5] - mnz;
    const float ivx = GG / ex, ivy = GG / ey, ivz = GG / ez;
    const int cx = cell1(qx, mnx, ivx), cy = cell1(qy, mny, ivy), cz = cell1(qz, mnz, ivz);
    const float wmin = fminf(ex, fminf(ey, ez)) * (1.0f / GG);

    const float4* __restrict__ pts  = g_pts[b];
    const int*    __restrict__ pidx = g_pidx[b];
    const int*    __restrict__ cst  = g_cst[b];

    float ld = FLT_MAX;
    int   li = 0x7fffffff;
    float tau = FLT_MAX;

    // One warp-cooperative pass over a contiguous point range [PS, PE).
#define PROCESS(PS, PE)                                                         \
    for (int p0 = (PS); p0 < (PE); p0 += 32) {                                  \
        const int p = p0 + lane;                                                \
        const float4 cc = (p < (PE)) ? pts[p]                                   \
                                     : make_float4(0.f, 0.f, 0.f, FLT_MAX);     \
        float dot = qx * cc.x;                                                  \
        dot = fmaf(qy, cc.y, dot);                                              \
        dot = fmaf(qz, cc.z, dot);                                              \
        const float d2 = fmaf(-2.0f, dot, s0 + cc.w);                           \
        unsigned m = __ballot_sync(FULL, d2 < tau);                             \
        if (m) {                                                                \
            while (m) {                                                         \
                const int src = __ffs(m) - 1;                                   \
                m &= m - 1;                                                     \
                const float dv = __shfl_sync(FULL, d2, src);                    \
                const int   iv = pidx[p0 + src];                                \
                const float pd = __shfl_up_sync(FULL, ld, 1, 16);               \
                const int   pi2 = __shfl_up_sync(FULL, li, 1, 16);              \
                const bool ct = lex_less(dv, iv, ld, li);                       \
                const bool cp = (t > 0) && lex_less(dv, iv, pd, pi2);           \
                if (lane < 16 && ct) { ld = cp ? pd : dv; li = cp ? pi2 : iv; } \
            }                                                                   \
            tau = __shfl_sync(FULL, ld, 15);                                    \
        }                                                                       \
    }

    for (int r = 0;; r++) {
        const int z0 = max(cz - r, 0), z1 = min(cz + r, GG - 1);
        for (int z = z0; z <= z1; z++) {
            const int adz = (z > cz) ? (z - cz) : (cz - z);
            const int y0 = max(cy - r, 0), y1 = min(cy + r, GG - 1);
            for (int y = y0; y <= y1; y++) {
                const int ady = (y > cy) ? (y - cy) : (cy - y);
                const int rowb = (z * GG + y) * GG;
                if (adz == r || ady == r) {
                    // full row: cells cx-r..cx+r are contiguous -> one point range
                    const int x0 = max(cx - r, 0), x1 = min(cx + r, GG - 1);
                    const int ps = cst[rowb + x0], pe = cst[rowb + x1 + 1];
                    PROCESS(ps, pe);
                } else {
                    // interior row: only the two boundary cells are new
                    const int xl = cx - r;
                    if (xl >= 0) {
                        const int ps = cst[rowb + xl], pe = cst[rowb + xl + 1];
                        PROCESS(ps, pe);
                    }
                    const int xr = cx + r;
                    if (xr < GG) {
                        const int ps = cst[rowb + xr], pe = cst[rowb + xr + 1];
                        PROCESS(ps, pe);
                    }
                }
            }
        }
        // After ring r: unvisited cells are at distance >= r*wmin.
        const float bnd = (float)r * wmin;
        if (tau < FLT_MAX && tau <= 0.98f * bnd * bnd) break;
        if (r > GG) break;   // everything visited
    }
#undef PROCESS

    // ---- Epilogue: features [B, N, K, 10] then indices [B, N, K] as float ----
    if (lane < 16) {
        const size_t qlin = (size_t)b * NN + q;
        const size_t feat_total = (size_t)BB * NN * KK * 10;
        const bool write_idx = ((size_t)out_size >= feat_total + (size_t)BB * NN * KK);

        const int j = li;
        const float nx = base[3 * j + 0];
        const float ny = base[3 * j + 1];
        const float nz = base[3 * j + 2];

        float* p = out + qlin * KK * 10 + (size_t)t * 10;
        p[0] = ld;
        p[1] = qx - nx;
        p[2] = qy - ny;
        p[3] = qz - nz;
        p[4] = qx;
        p[5] = qy;
        p[6] = qz;
        p[7] = nx;
        p[8] = ny;
        p[9] = nz;
        if (write_idx) out[feat_total + qlin * KK + t] = (float)j;
    }
}

extern "C" void kernel_launch(void* const* d_in, const int* in_sizes, int n_in,
                              void* d_out, int out_size) {
    const float* xyz = (const float*)d_in[0];
    float* out = (float*)d_out;

    k_init<<<(BB * NC + 255) / 256, 256>>>();
    k_bbox<<<BB, 1024>>>(xyz);
    k_count<<<(BB * NN + 255) / 256, 256>>>(xyz);
    k_scan<<<BB, 1024>>>();
    k_scatter<<<(BB * NN + 255) / 256, 256>>>(xyz);
    k_search<<<(BB * NN) / SW, SW * 32>>>(xyz, out, out_size);
}

// round 8
// speedup vs baseline: 1.9775x; 1.9775x over previous
#include <cuda_runtime.h>
#include <cfloat>

// Problem constants (reference: xyz [4, 8192, 3], K=16)
#define BB   4
#define NN   8192
#define GG   24
#define NC   (GG * GG * GG)       // 13824
#define NBLK (NC / 256)           // 54 scan blocks per batch
#define KK   16
#define SW   4                    // warps per search block
#define FULL 0xffffffffu

// ---- device scratch (static: allocation-free) ----
__device__ float4 g_pts[BB][NN];        // cell-sorted points (x,y,z,|x|^2)
__device__ int    g_pidx[BB][NN];       // original indices, cell-sorted
__device__ int    g_cnt[BB][NC];        // per-cell counts
__device__ int    g_cst[BB][NC + 1];    // per-cell start offsets
__device__ int    g_cur[BB][NC];        // scatter cursors
__device__ int    g_bsum[BB][NBLK];     // scan block sums
__device__ int    g_boff[BB][NBLK];     // scan block offsets
__device__ float  g_bb[BB][6];          // minx,miny,minz,maxx,maxy,maxz

__device__ __forceinline__ bool lex_less(float d, int i, float ed, int ei) {
    return (d < ed) || (d == ed && i < ei);
}

// Ascending lexicographic bitonic sort of 32 (d,i) pairs across the warp.
__device__ __forceinline__ void bitonic32(float& d, int& i, int lane) {
#pragma unroll
    for (int k = 2; k <= 32; k <<= 1) {
#pragma unroll
        for (int j = k >> 1; j > 0; j >>= 1) {
            const float od = __shfl_xor_sync(FULL, d, j);
            const int   oi = __shfl_xor_sync(FULL, i, j);
            const bool keep_min = ((lane & k) == 0) == ((lane & j) == 0);
            const bool less = lex_less(od, oi, d, i);
            if (keep_min == less) { d = od; i = oi; }
        }
    }
}

// ---- 1: zero counts ----
__global__ void k_init() {
    const int i = blockIdx.x * blockDim.x + threadIdx.x;
    if (i < BB * NC) ((int*)g_cnt)[i] = 0;
}

// ---- 2: per-batch bbox (1 block per batch) ----
__global__ void k_bbox(const float* __restrict__ xyz) {
    const int b = blockIdx.x;
    const float* base = xyz + (size_t)b * NN * 3;
    float mn0 = FLT_MAX, mn1 = FLT_MAX, mn2 = FLT_MAX;
    float mx0 = -FLT_MAX, mx1 = -FLT_MAX, mx2 = -FLT_MAX;
    for (int i = threadIdx.x; i < NN; i += blockDim.x) {
        const float x = base[3 * i + 0], y = base[3 * i + 1], z = base[3 * i + 2];
        mn0 = fminf(mn0, x); mx0 = fmaxf(mx0, x);
        mn1 = fminf(mn1, y); mx1 = fmaxf(mx1, y);
        mn2 = fminf(mn2, z); mx2 = fmaxf(mx2, z);
    }
#pragma unroll
    for (int o = 16; o; o >>= 1) {
        mn0 = fminf(mn0, __shfl_xor_sync(FULL, mn0, o));
        mn1 = fminf(mn1, __shfl_xor_sync(FULL, mn1, o));
        mn2 = fminf(mn2, __shfl_xor_sync(FULL, mn2, o));
        mx0 = fmaxf(mx0, __shfl_xor_sync(FULL, mx0, o));
        mx1 = fmaxf(mx1, __shfl_xor_sync(FULL, mx1, o));
        mx2 = fmaxf(mx2, __shfl_xor_sync(FULL, mx2, o));
    }
    __shared__ float s[6][32];
    const int w = threadIdx.x >> 5, l = threadIdx.x & 31;
    if (l == 0) {
        s[0][w] = mn0; s[1][w] = mn1; s[2][w] = mn2;
        s[3][w] = mx0; s[4][w] = mx1; s[5][w] = mx2;
    }
    __syncthreads();
    if (w == 0) {
        const int nw = blockDim.x >> 5;
        float a0 = (l < nw) ? s[0][l] : FLT_MAX;
        float a1 = (l < nw) ? s[1][l] : FLT_MAX;
        float a2 = (l < nw) ? s[2][l] : FLT_MAX;
        float b0 = (l < nw) ? s[3][l] : -FLT_MAX;
        float b1 = (l < nw) ? s[4][l] : -FLT_MAX;
        float b2 = (l < nw) ? s[5][l] : -FLT_MAX;
#pragma unroll
        for (int o = 16; o; o >>= 1) {
            a0 = fminf(a0, __shfl_xor_sync(FULL, a0, o));
            a1 = fminf(a1, __shfl_xor_sync(FULL, a1, o));
            a2 = fminf(a2, __shfl_xor_sync(FULL, a2, o));
            b0 = fmaxf(b0, __shfl_xor_sync(FULL, b0, o));
            b1 = fmaxf(b1, __shfl_xor_sync(FULL, b1, o));
            b2 = fmaxf(b2, __shfl_xor_sync(FULL, b2, o));
        }
        if (l == 0) {
            g_bb[b][0] = a0 - 1e-4f; g_bb[b][1] = a1 - 1e-4f; g_bb[b][2] = a2 - 1e-4f;
            g_bb[b][3] = b0 + 1e-4f; g_bb[b][4] = b1 + 1e-4f; g_bb[b][5] = b2 + 1e-4f;
        }
    }
}

// Cell assignment — SAME formula everywhere (count/scatter/search).
__device__ __forceinline__ int cell1(float v, float mn, float inv) {
    int c = (int)((v - mn) * inv);
    return min(GG - 1, max(0, c));
}

// ---- 3: count points per cell ----
__global__ void k_count(const float* __restrict__ xyz) {
    const int gi = blockIdx.x * blockDim.x + threadIdx.x;
    if (gi >= BB * NN) return;
    const int b = gi >> 13, i = gi & (NN - 1);
    const float* base = xyz + (size_t)b * NN * 3;
    const float x = base[3 * i + 0], y = base[3 * i + 1], z = base[3 * i + 2];
    const float mnx = g_bb[b][0], mny = g_bb[b][1], mnz = g_bb[b][2];
    const float ivx = GG / (g_bb[b][3] - mnx);
    const float ivy = GG / (g_bb[b][4] - mny);
    const float ivz = GG / (g_bb[b][5] - mnz);
    const int cx = cell1(x, mnx, ivx), cy = cell1(y, mny, ivy), cz = cell1(z, mnz, ivz);
    atomicAdd(&g_cnt[b][(cz * GG + cy) * GG + cx], 1);
}

// ---- 4a: per-block local scan (256 cells per block, BB*NBLK blocks) ----
__global__ __launch_bounds__(256)
void k_scan1() {
    const int blk = blockIdx.x;
    const int b = blk / NBLK, lb = blk - b * NBLK;
    const int cell = lb * 256 + threadIdx.x;
    const int lane = threadIdx.x & 31, wid = threadIdx.x >> 5;

    const int c = g_cnt[b][cell];
    int s = c;
#pragma unroll
    for (int o = 1; o < 32; o <<= 1) {
        const int v = __shfl_up_sync(FULL, s, o);
        if (lane >= o) s += v;
    }
    __shared__ int wsum[8];
    if (lane == 31) wsum[wid] = s;
    __syncthreads();
    if (threadIdx.x < 8) {
        int x = wsum[threadIdx.x];
        int e = x;
#pragma unroll
        for (int o = 1; o < 8; o <<= 1) {
            const int v = __shfl_up_sync(0xffu, e, o);
            if (threadIdx.x >= o) e += v;
        }
        wsum[threadIdx.x] = e - x;        // exclusive warp base
    }
    __syncthreads();
    const int excl = s - c + wsum[wid];
    g_cst[b][cell] = excl;                // local (pre-offset) exclusive scan
    if (threadIdx.x == 255) g_bsum[b][lb] = excl + c;   // block total
}

// ---- 4b: scan of block sums (1 tiny block, 1 warp per batch) ----
__global__ void k_scan2() {
    const int b = threadIdx.x >> 5, l = threadIdx.x & 31;
    if (b >= BB) return;
    int v0 = g_bsum[b][l];                // NBLK=54 > 32: first chunk all valid
    int s0 = v0;
#pragma unroll
    for (int o = 1; o < 32; o <<= 1) {
        const int v = __shfl_up_sync(FULL, s0, o);
        if (l >= o) s0 += v;
    }
    const int t0 = __shfl_sync(FULL, s0, 31);
    const int i1 = 32 + l;
    int v1 = (i1 < NBLK) ? g_bsum[b][i1] : 0;
    int s1 = v1;
#pragma unroll
    for (int o = 1; o < 32; o <<= 1) {
        const int v = __shfl_up_sync(FULL, s1, o);
        if (l >= o) s1 += v;
    }
    s1 += t0;
    g_boff[b][l] = s0 - v0;
    if (i1 < NBLK) g_boff[b][i1] = s1 - v1;
    if (l == 0) g_cst[b][NC] = NN;
}

// ---- 4c: add block offsets, init cursors ----
__global__ __launch_bounds__(256)
void k_scan3() {
    const int blk = blockIdx.x;
    const int b = blk / NBLK, lb = blk - b * NBLK;
    const int cell = lb * 256 + threadIdx.x;
    const int v = g_cst[b][cell] + g_boff[b][lb];
    g_cst[b][cell] = v;
    g_cur[b][cell] = v;
}

// ---- 5: scatter points into cell-sorted order ----
__global__ void k_scatter(const float* __restrict__ xyz) {
    const int gi = blockIdx.x * blockDim.x + threadIdx.x;
    if (gi >= BB * NN) return;
    const int b = gi >> 13, i = gi & (NN - 1);
    const float* base = xyz + (size_t)b * NN * 3;
    const float x = base[3 * i + 0], y = base[3 * i + 1], z = base[3 * i + 2];
    const float mnx = g_bb[b][0], mny = g_bb[b][1], mnz = g_bb[b][2];
    const float ivx = GG / (g_bb[b][3] - mnx);
    const float ivy = GG / (g_bb[b][4] - mny);
    const float ivz = GG / (g_bb[b][5] - mnz);
    const int cx = cell1(x, mnx, ivx), cy = cell1(y, mny, ivy), cz = cell1(z, mnz, ivz);
    const int pos = atomicAdd(&g_cur[b][(cz * GG + cy) * GG + cx], 1);
    g_pts[b][pos] = make_float4(x, y, z, x * x + y * y + z * z);   // frozen R1 form
    g_pidx[b][pos] = i;
}

// ---- 6: per-query expanding-ring exact kNN + feature epilogue ----
__global__ __launch_bounds__(SW * 32)
void k_search(const float* __restrict__ xyz, float* __restrict__ out, int out_size) {
    const int lane = threadIdx.x & 31;
    const int wid  = threadIdx.x >> 5;
    const int qg = blockIdx.x * SW + wid;      // 0..BB*NN-1
    const int b = qg >> 13;
    const int q = qg & (NN - 1);
    const int t = lane & 15;

    const float* __restrict__ base = xyz + (size_t)b * NN * 3;
    const float qx = base[3 * q + 0], qy = base[3 * q + 1], qz = base[3 * q + 2];
    const float s0 = qx * qx + qy * qy + qz * qz;          // frozen R1 form

    const float mnx = g_bb[b][0], mny = g_bb[b][1], mnz = g_bb[b][2];
    const float ex = g_bb[b][3] - mnx, ey = g_bb[b][4] - mny, ez = g_bb[b][5] - mnz;
    const float ivx = GG / ex, ivy = GG / ey, ivz = GG / ez;
    const int cx = cell1(qx, mnx, ivx), cy = cell1(qy, mny, ivy), cz = cell1(qz, mnz, ivz);
    const float wmin = fminf(ex, fminf(ey, ez)) * (1.0f / GG);

    const float4* __restrict__ pts  = g_pts[b];
    const int*    __restrict__ pidx = g_pidx[b];
    const int*    __restrict__ cst  = g_cst[b];

    float ld = FLT_MAX;
    int   li = 0x7fffffff;
    float tau = FLT_MAX;

    // One warp-cooperative pass over a contiguous point range [PS, PE).
#define PROCESS(PS, PE)                                                         \
    for (int p0 = (PS); p0 < (PE); p0 += 32) {                                  \
        const int p = p0 + lane;                                                \
        const bool ok = (p < (PE));                                             \
        const float4 cc = ok ? pts[p] : make_float4(0.f, 0.f, 0.f, FLT_MAX);    \
        const int   ci = ok ? pidx[p] : 0x7fffffff;                             \
        float dot = qx * cc.x;                                                  \
        dot = fmaf(qy, cc.y, dot);                                              \
        dot = fmaf(qz, cc.z, dot);                                              \
        const float d2 = fmaf(-2.0f, dot, s0 + cc.w);                           \
        unsigned m = __ballot_sync(FULL, d2 < tau);                             \
        if (m) {                                                                \
            while (m) {                                                         \
                const int src = __ffs(m) - 1;                                   \
                m &= m - 1;                                                     \
                const float dv = __shfl_sync(FULL, d2, src);                    \
                const int   iv = __shfl_sync(FULL, ci, src);                    \
                const float pd = __shfl_up_sync(FULL, ld, 1, 16);               \
                const int   pi2 = __shfl_up_sync(FULL, li, 1, 16);              \
                const bool ct = lex_less(dv, iv, ld, li);                       \
                const bool cp = (t > 0) && lex_less(dv, iv, pd, pi2);           \
                if (lane < 16 && ct) { ld = cp ? pd : dv; li = cp ? pi2 : iv; } \
            }                                                                   \
            tau = __shfl_sync(FULL, ld, 15);                                    \
        }                                                                       \
    }

    // ---- Ring 0 (home cell) with bitonic warmup on the first 32 candidates ----
    {
        const int c0 = (cz * GG + cy) * GG + cx;
        const int ps = cst[c0], pe = cst[c0 + 1];
        const int p = ps + lane;
        const bool ok = (p < pe);
        const float4 cc = ok ? pts[p] : make_float4(0.f, 0.f, 0.f, FLT_MAX);
        const int   ci = ok ? pidx[p] : 0x7fffffff;
        float dot = qx * cc.x;
        dot = fmaf(qy, cc.y, dot);
        dot = fmaf(qz, cc.z, dot);
        float d = ok ? fmaf(-2.0f, dot, s0 + cc.w) : FLT_MAX;
        int   i = ci;
        bitonic32(d, i, lane);
        ld = d;                      // lanes 0-15 = sorted list; 16-31 unused
        li = i;
        tau = __shfl_sync(FULL, ld, 15);
        PROCESS(ps + 32, pe);
    }

    // ---- Rings r >= 1 ----
    for (int r = 1;; r++) {
        const int z0 = max(cz - r, 0), z1 = min(cz + r, GG - 1);
        for (int z = z0; z <= z1; z++) {
            const int adz = (z > cz) ? (z - cz) : (cz - z);
            const int y0 = max(cy - r, 0), y1 = min(cy + r, GG - 1);
            for (int y = y0; y <= y1; y++) {
                const int ady = (y > cy) ? (y - cy) : (cy - y);
                const int rowb = (z * GG + y) * GG;
                if (adz == r || ady == r) {
                    const int x0 = max(cx - r, 0), x1 = min(cx + r, GG - 1);
                    const int ps = cst[rowb + x0], pe = cst[rowb + x1 + 1];
                    PROCESS(ps, pe);
                } else {
                    const int xl = cx - r;
                    if (xl >= 0) {
                        const int ps = cst[rowb + xl], pe = cst[rowb + xl + 1];
                        PROCESS(ps, pe);
                    }
                    const int xr = cx + r;
                    if (xr < GG) {
                        const int ps = cst[rowb + xr], pe = cst[rowb + xr + 1];
                        PROCESS(ps, pe);
                    }
                }
            }
        }
        const float bnd = (float)r * wmin;
        if (tau < FLT_MAX && tau <= 0.98f * bnd * bnd) break;
        if (r > GG) break;
    }
#undef PROCESS

    // ---- Epilogue: features [B, N, K, 10] then indices [B, N, K] as float ----
    if (lane < 16) {
        const size_t qlin = (size_t)b * NN + q;
        const size_t feat_total = (size_t)BB * NN * KK * 10;
        const bool write_idx = ((size_t)out_size >= feat_total + (size_t)BB * NN * KK);

        const int j = li;
        const float nx = base[3 * j + 0];
        const float ny = base[3 * j + 1];
        const float nz = base[3 * j + 2];

        float* p = out + qlin * KK * 10 + (size_t)t * 10;
        p[0] = ld;
        p[1] = qx - nx;
        p[2] = qy - ny;
        p[3] = qz - nz;
        p[4] = qx;
        p[5] = qy;
        p[6] = qz;
        p[7] = nx;
        p[8] = ny;
        p[9] = nz;
        if (write_idx) out[feat_total + qlin * KK + t] = (float)j;
    }
}

extern "C" void kernel_launch(void* const* d_in, const int* in_sizes, int n_in,
                              void* d_out, int out_size) {
    const float* xyz = (const float*)d_in[0];
    float* out = (float*)d_out;

    k_init<<<(BB * NC + 255) / 256, 256>>>();
    k_bbox<<<BB, 1024>>>(xyz);
    k_count<<<(BB * NN + 255) / 256, 256>>>(xyz);
    k_scan1<<<BB * NBLK, 256>>>();
    k_scan2<<<1, BB * 32>>>();
    k_scan3<<<BB * NBLK, 256>>>();
    k_scatter<<<(BB * NN + 255) / 256, 256>>>(xyz);
    k_search<<<(BB * NN) / SW, SW * 32>>>(xyz, out, out_size);
}